// round 5
// baseline (speedup 1.0000x reference)
#include <cuda_runtime.h>
#include <cuda_bf16.h>
#include <cstdint>

// ============================================================================
// FloReLBlock via mma.sync split-bf16 GEMMs (tcgen05 unavailable: harness
// targets compute_103 without 'a').
// R5: GEMM3 retiled 128x64 and scheduled FIRST in the fat kernel (long CTAs
// start in wave 1); GEMM1 retiled 128x64 -> 256 CTAs (full wave); fp32 h
// buffer dropped (h reconstructed from hi+lo bf16 in the div epilogue).
// ============================================================================

constexpr int Bn  = 2048;
constexpr int Dn  = 512;
constexpr int Hn  = 1024;
constexpr int DP1 = Dn + 1;

// -------------------- device scratch ----------------------------------------
__device__ float g_state[Bn * DP1];
__device__ float g_kbuf[4][Bn * DP1];
__device__ float g_div[5 * 2 * Bn];        // slices 0..4 (stage0 double-buffered 0/4)

__device__ __align__(16) __nv_bfloat16 g_z_hi[Bn * Dn];
__device__ __align__(16) __nv_bfloat16 g_z_lo[Bn * Dn];
__device__ __align__(16) __nv_bfloat16 g_e   [2 * Bn * Dn];
__device__ __align__(16) __nv_bfloat16 g_h_hi[Bn * Hn];
__device__ __align__(16) __nv_bfloat16 g_h_lo[Bn * Hn];
__device__ __align__(16) __nv_bfloat16 g_W1T_hi[Hn * Dn];      // [H x D] (N x K)
__device__ __align__(16) __nv_bfloat16 g_W1T_lo[Hn * Dn];
__device__ __align__(16) __nv_bfloat16 g_Wc_hi[2 * Hn * Dn];   // interleaved W1T/W2 rows
__device__ __align__(16) __nv_bfloat16 g_Wc_lo[2 * Hn * Dn];
__device__ __align__(16) __nv_bfloat16 g_W2T_hi[Dn * Hn];      // [D x H] (N x K)
__device__ __align__(16) __nv_bfloat16 g_W2T_lo[Dn * Hn];

// -------------------- threefry2x32 (exact JAX, partitionable) ---------------
__host__ __device__ __forceinline__ void tf2x32(
    uint32_t k0, uint32_t k1, uint32_t x0, uint32_t x1,
    uint32_t& o0, uint32_t& o1)
{
    const uint32_t ks0 = k0;
    const uint32_t ks1 = k1;
    const uint32_t ks2 = 0x1BD11BDAu ^ k0 ^ k1;
    x0 += ks0; x1 += ks1;
#define TFR(r) { x0 += x1; x1 = (x1 << (r)) | (x1 >> (32 - (r))); x1 ^= x0; }
    TFR(13) TFR(15) TFR(26) TFR(6)
    x0 += ks1; x1 += ks2 + 1u;
    TFR(17) TFR(29) TFR(16) TFR(24)
    x0 += ks2; x1 += ks0 + 2u;
    TFR(13) TFR(15) TFR(26) TFR(6)
    x0 += ks0; x1 += ks1 + 3u;
    TFR(17) TFR(29) TFR(16) TFR(24)
    x0 += ks1; x1 += ks2 + 4u;
    TFR(13) TFR(15) TFR(26) TFR(6)
    x0 += ks2; x1 += ks0 + 5u;
#undef TFR
    o0 = x0; o1 = x1;
}

// -------------------- helpers -----------------------------------------------
__device__ __forceinline__ void split2(float v, __nv_bfloat16& hi, __nv_bfloat16& lo) {
    hi = __float2bfloat16(v);
    lo = __float2bfloat16(v - __bfloat162float(hi));
}

__device__ __forceinline__ uint32_t smem_u32(const void* p) {
    uint32_t a;
    asm("{ .reg .u64 t; cvta.to.shared.u64 t, %1; cvt.u32.u64 %0, t; }" : "=r"(a) : "l"(p));
    return a;
}

__device__ __forceinline__ void cpasync16(uint32_t dst, const void* src) {
    asm volatile("cp.async.cg.shared.global [%0], [%1], 16;" :: "r"(dst), "l"(src));
}
#define CP_COMMIT() asm volatile("cp.async.commit_group;" ::: "memory")

__device__ __forceinline__ uint32_t swz64(uint32_t x) {   // 64B-row swizzle
    return x ^ ((x >> 3) & 0x30u);
}

__device__ __forceinline__ void ldsm_x4(uint32_t& r0, uint32_t& r1, uint32_t& r2, uint32_t& r3, uint32_t addr) {
    asm volatile("ldmatrix.sync.aligned.m8n8.x4.shared.b16 {%0,%1,%2,%3}, [%4];"
                 : "=r"(r0), "=r"(r1), "=r"(r2), "=r"(r3) : "r"(addr));
}

__device__ __forceinline__ void mma16816(
    float* d, const uint32_t* a, const uint32_t* b)
{
    asm volatile(
        "mma.sync.aligned.m16n8k16.row.col.f32.bf16.bf16.f32 "
        "{%0,%1,%2,%3}, {%4,%5,%6,%7}, {%8,%9}, {%0,%1,%2,%3};"
        : "+f"(d[0]), "+f"(d[1]), "+f"(d[2]), "+f"(d[3])
        : "r"(a[0]), "r"(a[1]), "r"(a[2]), "r"(a[3]), "r"(b[0]), "r"(b[1]));
}

__device__ __forceinline__ float blockReduceSum256(float v) {
    __shared__ float sh[8];
    #pragma unroll
    for (int o = 16; o > 0; o >>= 1) v += __shfl_down_sync(0xffffffffu, v, o);
    const int lane = threadIdx.x & 31;
    const int w    = threadIdx.x >> 5;
    if (lane == 0) sh[w] = v;
    __syncthreads();
    if (w == 0) {
        v = (lane < 8) ? sh[lane] : 0.f;
        #pragma unroll
        for (int o = 4; o > 0; o >>= 1) v += __shfl_down_sync(0xffffffffu, v, o);
    }
    return v;
}

__device__ __forceinline__ __nv_bfloat16 rad_bf16(uint32_t bits) {
    return __float2bfloat16((bits & 1u) ? 1.f : -1.f);
}

// -------------------- elementwise kernels -----------------------------------
__global__ void __launch_bounds__(256) prep_weights_kernel(
    const float* __restrict__ W1, const float* __restrict__ W2)
{
    int i = blockIdx.x * 256 + threadIdx.x;
    if (i < Hn * Dn) {
        int j = i / Dn, d = i % Dn;
        __nv_bfloat16 hi, lo;
        split2(W1[(size_t)d * Hn + j], hi, lo);
        g_W1T_hi[(size_t)j * Dn + d] = hi;
        g_W1T_lo[(size_t)j * Dn + d] = lo;
        g_Wc_hi[(size_t)(2 * j) * Dn + d] = hi;
        g_Wc_lo[(size_t)(2 * j) * Dn + d] = lo;
        split2(W2[(size_t)j * Dn + d], hi, lo);
        g_Wc_hi[(size_t)(2 * j + 1) * Dn + d] = hi;
        g_Wc_lo[(size_t)(2 * j + 1) * Dn + d] = lo;
        g_W2T_hi[(size_t)d * Hn + j] = hi;
        g_W2T_lo[(size_t)d * Hn + j] = lo;
    }
}

__global__ void __launch_bounds__(256) init_kernel(
    const float* __restrict__ x,
    uint32_t a0, uint32_t b0, uint32_t a1, uint32_t b1)
{
    int i = blockIdx.x * 256 + threadIdx.x;
    if (i < 2 * Bn) g_div[i] = 0.f;
    if (i >= Bn * DP1) return;
    int b = i / DP1, c = i % DP1;
    float v = (c < Dn) ? x[b * Dn + c] : 0.f;
    g_state[i] = v;
    if (c < Dn) {
        int j = b * Dn + c;
        split2(v, g_z_hi[j], g_z_lo[j]);
        uint32_t o0, o1;
        tf2x32(a0, b0, 0u, (uint32_t)j, o0, o1);
        g_e[j] = rad_bf16(o0 ^ o1);
        tf2x32(a1, b1, 0u, (uint32_t)j, o0, o1);
        g_e[Bn * Dn + j] = rad_bf16(o0 ^ o1);
    }
}

__global__ void __launch_bounds__(256) stage_prep_kernel(
    float c1, float c2, float c3,
    uint32_t a0, uint32_t b0, uint32_t a1, uint32_t b1, int divslot)
{
    int i = blockIdx.x * 256 + threadIdx.x;
    if (i < 2 * Bn) g_div[divslot * 2 * Bn + i] = 0.f;
    if (i >= Bn * Dn) return;
    int b = i >> 9, d = i & 511;
    int idx = b * DP1 + d;
    float v = g_state[idx] + c1 * g_kbuf[0][idx] + c2 * g_kbuf[1][idx] + c3 * g_kbuf[2][idx];
    split2(v, g_z_hi[i], g_z_lo[i]);
    uint32_t o0, o1;
    tf2x32(a0, b0, 0u, (uint32_t)i, o0, o1);
    g_e[i] = rad_bf16(o0 ^ o1);
    tf2x32(a1, b1, 0u, (uint32_t)i, o0, o1);
    g_e[Bn * Dn + i] = rad_bf16(o0 ^ o1);
}

__global__ void __launch_bounds__(256) update_prep_kernel(
    float w, int slot0_cur, int slot0_next,
    uint32_t a0, uint32_t b0, uint32_t a1, uint32_t b1)
{
    int i = blockIdx.x * 256 + threadIdx.x;
    if (i < 2 * Bn) g_div[slot0_next * 2 * Bn + i] = 0.f;
    if (i >= Bn * DP1) return;
    int b = i / DP1, c = i % DP1;
    if (c < Dn) {
        float delta = g_kbuf[0][i] + 3.f * (g_kbuf[1][i] + g_kbuf[2][i]) + g_kbuf[3][i];
        float v = g_state[i] + w * delta;
        g_state[i] = v;
        int j = b * Dn + c;
        split2(v, g_z_hi[j], g_z_lo[j]);
        uint32_t o0, o1;
        tf2x32(a0, b0, 0u, (uint32_t)j, o0, o1);
        g_e[j] = rad_bf16(o0 ^ o1);
        tf2x32(a1, b1, 0u, (uint32_t)j, o0, o1);
        g_e[Bn * Dn + j] = rad_bf16(o0 ^ o1);
    } else {
        const float coef[4] = {1.f, 3.f, 3.f, 1.f};
        float comb = 0.f;
        #pragma unroll
        for (int st = 0; st < 4; ++st) {
            int slot = (st == 0) ? slot0_cur : st;
            float dv = 0.5f * (g_div[slot * 2 * Bn + b] + g_div[slot * 2 * Bn + Bn + b]);
            dv = fminf(fmaxf(dv, -100.f), 100.f);
            comb += coef[st] * (-dv);
        }
        g_state[i] += w * comb;
    }
}

__global__ void __launch_bounds__(256) finalize_kernel(float* __restrict__ out) {
    const int b = blockIdx.x;
    const float* row = g_state + (size_t)b * DP1;
    float acc = 0.f;
    for (int d = threadIdx.x; d < Dn; d += 256) {
        float v = row[d];
        out[(size_t)b * Dn + d] = v;
        acc += v * v;
    }
    float tot = blockReduceSum256(acc);
    if (threadIdx.x == 0)
        out[(size_t)Bn * Dn + b] = -0.5f * tot + row[Dn];
}

// -------------------- mma.sync GEMM body ------------------------------------
// CTA tile 128 x BN, K-chunk 32 (64B rows, SW64 swizzle), 8 warps (4M x 2N,
// warp tile 32 x BN/2), double buffered.
// MODE 0 (BN=64):  h = tanh(acc + b1 + t*tw1), K=512, 3 terms
// MODE 1 (BN=128): Hutchinson div (interleaved Wc), K=512, 2 terms -> g_div
// MODE 2 (BN=64):  k = acc + b2, K=1024, 3 terms -> g_kbuf
constexpr int TILE_A = 8192;   // 128 rows x 64 bytes

template <int MODE, int BN>
__device__ __forceinline__ void gemm_body(
    int bx, int by, const float* __restrict__ bias,
    const float* __restrict__ tvec, float t, int arg, char* smem)
{
    constexpr int K   = (MODE == 2) ? 1024 : 512;
    constexpr int NC  = K / 32;
    constexpr int NT  = (MODE == 1) ? 2 : 3;
    constexpr int WTN = BN / 2;           // warp tile N
    constexpr int NF  = WTN / 8;          // 8-wide n-frags per warp
    constexpr int NP  = WTN / 16;         // ldsm x4 B loads per k16
    constexpr int TILE_BB = BN * 64;      // B tile bytes

    constexpr uint32_t offA0 = 0;
    constexpr uint32_t offA1 = (NT == 3) ? TILE_A : 0;
    constexpr uint32_t offB0 = (NT == 3) ? 2 * TILE_A : TILE_A;
    constexpr uint32_t offB1 = offB0 + TILE_BB;
    constexpr uint32_t STAGE = offB1 + TILE_BB;

    const uint32_t sb = smem_u32(smem);
    const int tid = threadIdx.x;
    const int wid = tid >> 5;
    const int ln  = tid & 31;
    const int m0  = by * 128;
    const int n0  = bx * BN;
    const int wm  = (wid >> 1) * 32;
    const int wn  = (wid & 1) * WTN;

    const __nv_bfloat16 *A0, *A1, *B0, *B1;
    if (MODE == 0)      { A0 = g_z_hi; A1 = g_z_lo;  B0 = g_W1T_hi; B1 = g_W1T_lo; }
    else if (MODE == 1) { A0 = g_e;    A1 = nullptr; B0 = g_Wc_hi;  B1 = g_Wc_lo;  }
    else                { A0 = g_h_hi; A1 = g_h_lo;  B0 = g_W2T_hi; B1 = g_W2T_lo; }

    // tile loaders (64B rows, SW64)
    auto ld_rows128 = [&](const __nv_bfloat16* g, int rbase, int kt, uint32_t toff) {
        #pragma unroll
        for (int it = 0; it < 2; ++it) {
            int idx = it * 256 + tid;
            int row = idx >> 2, u = idx & 3;
            uint32_t dst = sb + toff + swz64((uint32_t)(row * 64 + u * 16));
            cpasync16(dst, (const void*)(g + (size_t)(rbase + row) * K + kt + u * 8));
        }
    };
    auto ld_rows64 = [&](const __nv_bfloat16* g, int rbase, int kt, uint32_t toff) {
        int row = tid >> 2, u = tid & 3;
        uint32_t dst = sb + toff + swz64((uint32_t)(row * 64 + u * 16));
        cpasync16(dst, (const void*)(g + (size_t)(rbase + row) * K + kt + u * 8));
    };
    auto load_chunk = [&](int c, int st) {
        const int kt = c * 32;
        const uint32_t base = (uint32_t)st * STAGE;
        ld_rows128(A0, m0, kt, base + offA0);
        if (NT == 3) ld_rows128(A1, m0, kt, base + offA1);
        if (BN == 128) {
            ld_rows128(B0, n0, kt, base + offB0);
            ld_rows128(B1, n0, kt, base + offB1);
        } else {
            ld_rows64(B0, n0, kt, base + offB0);
            ld_rows64(B1, n0, kt, base + offB1);
        }
    };

    float acc[2][NF][4];
    #pragma unroll
    for (int mf = 0; mf < 2; ++mf)
        #pragma unroll
        for (int nf = 0; nf < NF; ++nf)
            #pragma unroll
            for (int i = 0; i < 4; ++i) acc[mf][nf][i] = 0.f;

    const int rowA = wm + (ln & 15);
    const int ucA  = (ln >> 4);
    const int rowB = wn + ((ln >> 4) << 3) + (ln & 7);
    const int ucB  = ((ln >> 3) & 1);

    load_chunk(0, 0); CP_COMMIT();

    for (int c = 0; c < NC; ++c) {
        if (c + 1 < NC) { load_chunk(c + 1, (c + 1) & 1); CP_COMMIT(); }
        if (c + 1 < NC) asm volatile("cp.async.wait_group 1;" ::: "memory");
        else            asm volatile("cp.async.wait_group 0;" ::: "memory");
        __syncthreads();

        const uint32_t base = sb + (uint32_t)(c & 1) * STAGE;
        #pragma unroll
        for (int k16 = 0; k16 < 2; ++k16) {
            uint32_t a0[2][4], a1[2][4];
            #pragma unroll
            for (int mf = 0; mf < 2; ++mf) {
                uint32_t off = swz64((uint32_t)((rowA + mf * 16) * 64 + (k16 * 2 + ucA) * 16));
                ldsm_x4(a0[mf][0], a0[mf][1], a0[mf][2], a0[mf][3], base + offA0 + off);
                if (NT == 3)
                    ldsm_x4(a1[mf][0], a1[mf][1], a1[mf][2], a1[mf][3], base + offA1 + off);
            }
            #pragma unroll
            for (int np = 0; np < NP; ++np) {
                uint32_t b0[2][2], b1[2][2];
                uint32_t off = swz64((uint32_t)((rowB + np * 16) * 64 + (k16 * 2 + ucB) * 16));
                ldsm_x4(b0[0][0], b0[0][1], b0[1][0], b0[1][1], base + offB0 + off);
                ldsm_x4(b1[0][0], b1[0][1], b1[1][0], b1[1][1], base + offB1 + off);
                #pragma unroll
                for (int mf = 0; mf < 2; ++mf)
                    #pragma unroll
                    for (int nl = 0; nl < 2; ++nl) {
                        const int nf = 2 * np + nl;
                        mma16816(acc[mf][nf], a0[mf], b0[nl]);
                        mma16816(acc[mf][nf], a0[mf], b1[nl]);
                        if (NT == 3) mma16816(acc[mf][nf], a1[mf], b0[nl]);
                    }
            }
        }
        __syncthreads();
    }

    // ---- epilogue ----
    if (MODE == 0) {
        #pragma unroll
        for (int mf = 0; mf < 2; ++mf) {
            #pragma unroll
            for (int i2 = 0; i2 < 2; ++i2) {
                const int m = m0 + wm + mf * 16 + (ln >> 2) + 8 * i2;
                #pragma unroll
                for (int nf = 0; nf < NF; ++nf) {
                    #pragma unroll
                    for (int j = 0; j < 2; ++j) {
                        const int n = n0 + wn + nf * 8 + (ln & 3) * 2 + j;
                        float v  = acc[mf][nf][i2 * 2 + j] + bias[n] + t * tvec[n];
                        float hh = tanhf(v);
                        size_t idx = (size_t)m * Hn + n;
                        __nv_bfloat16 hi = __float2bfloat16(hh);
                        g_h_hi[idx] = hi;
                        g_h_lo[idx] = __float2bfloat16(hh - __bfloat162float(hi));
                    }
                }
            }
        }
    } else if (MODE == 1) {
        #pragma unroll
        for (int mf = 0; mf < 2; ++mf) {
            #pragma unroll
            for (int i2 = 0; i2 < 2; ++i2) {
                const int m = m0 + wm + mf * 16 + (ln >> 2) + 8 * i2;
                const int b = m & (Bn - 1);
                float s = 0.f;
                #pragma unroll
                for (int nf = 0; nf < NF; ++nf) {
                    const int ncol = n0 + wn + nf * 8 + (ln & 3) * 2;
                    const float p0 = acc[mf][nf][i2 * 2 + 0];
                    const float p1 = acc[mf][nf][i2 * 2 + 1];
                    size_t idx = (size_t)b * Hn + (ncol >> 1);
                    const float hh = __bfloat162float(g_h_hi[idx]) + __bfloat162float(g_h_lo[idx]);
                    s += (1.f - hh * hh) * p0 * p1;
                }
                s += __shfl_xor_sync(0xffffffffu, s, 1);
                s += __shfl_xor_sync(0xffffffffu, s, 2);
                if ((ln & 3) == 0) atomicAdd(&g_div[arg * 2 * Bn + m], s);
            }
        }
    } else {
        float* kout = g_kbuf[arg];
        #pragma unroll
        for (int mf = 0; mf < 2; ++mf) {
            #pragma unroll
            for (int i2 = 0; i2 < 2; ++i2) {
                const int m = m0 + wm + mf * 16 + (ln >> 2) + 8 * i2;
                #pragma unroll
                for (int nf = 0; nf < NF; ++nf) {
                    #pragma unroll
                    for (int j = 0; j < 2; ++j) {
                        const int n = n0 + wn + nf * 8 + (ln & 3) * 2 + j;
                        kout[(size_t)m * DP1 + n] = acc[mf][nf][i2 * 2 + j] + bias[n];
                    }
                }
            }
        }
    }
}

constexpr int SMEM_SZ = 2 * (2 * TILE_A + 2 * 64 * 64);   // 49152 (all modes)

// GEMM1: 128x64 tiles, grid (16, 16)
__global__ void __launch_bounds__(256, 2) gemm1_kernel(
    const float* __restrict__ b1, const float* __restrict__ tw1, float t)
{
    extern __shared__ __align__(128) char smem[];
    gemm_body<0, 64>(blockIdx.x, blockIdx.y, b1, tw1, t, 0, smem);
}

// FAT: bids [0,128) = GEMM3 (128x64, long CTAs first), [128,640) = GEMM2 (128x128)
__global__ void __launch_bounds__(256, 2) gemm_fat_kernel(
    const float* __restrict__ b2, int kid, int divslot)
{
    extern __shared__ __align__(128) char smem[];
    const int bid = blockIdx.x;
    if (bid < 128) {
        gemm_body<2, 64>(bid & 7, bid >> 3, b2, nullptr, 0.f, kid, smem);
    } else {
        const int r = bid - 128;
        gemm_body<1, 128>(r & 15, r >> 4, nullptr, nullptr, 0.f, divslot, smem);
    }
}

// -------------------- host-side key schedule --------------------------------
struct KP { uint32_t a, b; };
static inline KP h_tf(KP k, uint32_t x0, uint32_t x1) {
    KP r; tf2x32(k.a, k.b, x0, x1, r.a, r.b); return r;
}
static inline KP lower_key(KP kq, uint32_t i) {
    KP folded = h_tf(kq, 0u, i);
    return h_tf(folded, 0u, 1u);
}

// -------------------- launcher ----------------------------------------------
extern "C" void kernel_launch(void* const* d_in, const int* in_sizes, int n_in,
                              void* d_out, int out_size)
{
    (void)in_sizes; (void)n_in; (void)out_size;
    const float* x   = (const float*)d_in[0];
    const float* W1  = (const float*)d_in[1];
    const float* b1  = (const float*)d_in[2];
    const float* tw1 = (const float*)d_in[3];
    const float* W2  = (const float*)d_in[4];
    const float* b2  = (const float*)d_in[5];
    float* out = (float*)d_out;

    static bool attr_done = false;
    if (!attr_done) {
        cudaFuncSetAttribute(gemm1_kernel,    cudaFuncAttributeMaxDynamicSharedMemorySize, SMEM_SZ);
        cudaFuncSetAttribute(gemm_fat_kernel, cudaFuncAttributeMaxDynamicSharedMemorySize, SMEM_SZ);
        attr_done = true;
    }

    // host key schedule
    KP lk[10][4][2];
    {
        KP key{ 0u, 1234u };
        for (int s = 0; s < 9; ++s) {
            KP ks5[5];
            for (uint32_t j = 0; j < 5; ++j) ks5[j] = h_tf(key, 0u, j);
            key = ks5[0];
            for (int st = 0; st < 4; ++st) {
                lk[s][st][0] = lower_key(ks5[1 + st], 0u);
                lk[s][st][1] = lower_key(ks5[1 + st], 1u);
            }
        }
        for (int st = 0; st < 4; ++st)
            lk[9][st][0] = lk[9][st][1] = KP{0u, 0u};
    }

    const int GRID_E = (Bn * DP1 + 255) / 256;
    const int GRID_Z = (Bn * Dn + 255) / 256;
    const float step = (float)(1.0 / 9.0);

    prep_weights_kernel<<<(Hn * Dn + 255) / 256, 256>>>(W1, W2);
    init_kernel<<<GRID_E, 256>>>(x, lk[0][0][0].a, lk[0][0][0].b, lk[0][0][1].a, lk[0][0][1].b);

    for (int s = 0; s < 9; ++s) {
        const float t0 = (float)s * step;
        const float t1 = (float)(s + 1) * step;
        const float dt = t1 - t0;
        const float tst[4] = { t0, t0 + dt / 3.0f, t0 + dt * 2.0f / 3.0f, t1 };
        const int slot0_cur  = (s & 1) ? 4 : 0;
        const int slot0_next = (s & 1) ? 0 : 4;

        for (int st = 0; st < 4; ++st) {
            if (st > 0) {
                float c1 = 0.f, c2 = 0.f, c3 = 0.f;
                if (st == 1)      { c1 = dt / 3.f; }
                else if (st == 2) { c1 = -dt / 3.f; c2 = dt; }
                else              { c1 = dt; c2 = -dt; c3 = dt; }
                stage_prep_kernel<<<GRID_Z, 256>>>(
                    c1, c2, c3,
                    lk[s][st][0].a, lk[s][st][0].b, lk[s][st][1].a, lk[s][st][1].b, st);
            }
            const int divslot = (st == 0) ? slot0_cur : st;
            gemm1_kernel<<<dim3(16, 16), 256, SMEM_SZ>>>(b1, tw1, tst[st]);
            gemm_fat_kernel<<<640, 256, SMEM_SZ>>>(b2, st, divslot);
        }
        update_prep_kernel<<<GRID_E, 256>>>(
            dt * 0.125f, slot0_cur, slot0_next,
            lk[s + 1][0][0].a, lk[s + 1][0][0].b, lk[s + 1][0][1].a, lk[s + 1][0][1].b);
    }

    finalize_kernel<<<Bn, 256>>>(out);
}